// round 5
// baseline (speedup 1.0000x reference)
#include <cuda_runtime.h>
#include <cuda_bf16.h>
#include <cfloat>

#define NN 2048
#define FF 64
#define KTOP 8
#define OUT_ROW ((KTOP + 1) * FF)   // 576

#define NBINS 512
#define BIN_HI 4.25f
#define BIN_W  (8.5f / (float)NBINS)
#define BIN_INVW ((float)NBINS / 8.5f)

#define SSTAGE 1024     // pairs staged in smem per block (8 KB)
#define BATCH 8
#define NSTEP (NN / 2)  // steps per parity stream

__device__ float2 g_binned[FF * NN];   // 1 MB scratch

__device__ __forceinline__ int bin_of(float v) {
    int b = (int)((BIN_HI - v) * BIN_INVW);
    return max(0, min(NBINS - 1, b));
}
__device__ __forceinline__ float remaining_bound(float v) {
    int b = bin_of(v);
    return (b == 0) ? FLT_MAX : (BIN_HI - (float)b * BIN_W + 1e-3f);
}
__device__ __forceinline__ void CE(float& a, float& b) {
    float hi = fmaxf(a, b), lo = fminf(a, b); a = hi; b = lo;
}

// ---------------------------------------------------------------------------
// Kernel 1: per-feature bucket binning (R3 version, proven ~5 us)
// ---------------------------------------------------------------------------
__global__ void __launch_bounds__(512) bin_cols_kernel(const float* __restrict__ x) {
    __shared__ float sx[NN];
    __shared__ int   cnt[NBINS];
    __shared__ int   sa[NBINS];
    __shared__ int   sb[NBINS];
    __shared__ int   cursor[NBINS];

    const int f   = blockIdx.x;
    const int tid = threadIdx.x;
    const int bs  = blockDim.x;

    for (int i = tid; i < NBINS; i += bs) cnt[i] = 0;
    __syncthreads();

    for (int i = tid; i < NN; i += bs) {
        float v = __ldg(&x[i * FF + f]);
        sx[i] = v;
        atomicAdd(&cnt[bin_of(v)], 1);
    }
    __syncthreads();

    for (int i = tid; i < NBINS; i += bs) sa[i] = cnt[i];
    __syncthreads();
    int* src = sa; int* dst = sb;
    for (int d = 1; d < NBINS; d <<= 1) {
        for (int i = tid; i < NBINS; i += bs)
            dst[i] = src[i] + ((i >= d) ? src[i - d] : 0);
        __syncthreads();
        int* t = src; src = dst; dst = t;
    }
    for (int i = tid; i < NBINS; i += bs) cursor[i] = src[i] - cnt[i];
    __syncthreads();

    float2* out = g_binned + (size_t)f * NN;
    for (int i = tid; i < NN; i += bs) {
        float v = sx[i];
        int pos = atomicAdd(&cursor[bin_of(v)], 1);
        out[pos] = make_float2(v, __int_as_float(i));
    }
}

// ---------------------------------------------------------------------------
// Kernel 2: pruned top-8 scan, warp-pair parity split.
// Block = 256 threads = 8 warps = 4 warp-pairs; each pair owns one
// (f, m-group-of-32). Warp parity 0 scans even candidates, parity 1 odd.
// 32 m per warp -> adj loads fully coalesced, insert amortized 32-wide.
// 1024 blocks -> 8192 warps (single resident wave).
// ---------------------------------------------------------------------------
__global__ void __launch_bounds__(256, 6) topk_scan_kernel(
        const float* __restrict__ adj,
        const float* __restrict__ x,
        float* __restrict__ out) {
    __shared__ float2 sp[SSTAGE];            // 8 KB: staged candidate pairs
    __shared__ float  sthr[8][32];           // 1 KB: per-warp arr[7] broadcast
    __shared__ float  smerge[4][KTOP][32];   // 4 KB: odd-parity results

    const int f      = blockIdx.x >> 4;           // 16 blocks per feature
    const int mgBase = (blockIdx.x & 15) * 4;
    const int warp   = threadIdx.x >> 5;
    const int lane   = threadIdx.x & 31;
    const int pair   = warp >> 1;                 // 0..3
    const int parity = warp & 1;
    const int m      = (mgBase + pair) * 32 + lane;

    const float2* __restrict__ pairs = g_binned + (size_t)f * NN;

    // init threshold slots, stage candidate list (block shares f)
    sthr[warp][lane] = -FLT_MAX;
    {
        const float4* s4 = (const float4*)pairs;
        float4* d4 = (float4*)sp;
        for (int i = threadIdx.x; i < SSTAGE / 2; i += blockDim.x)
            d4[i] = __ldg(s4 + i);
    }
    __syncthreads();

    volatile float* myThr = &sthr[warp][lane];
    volatile float* otThr = &sthr[warp ^ 1][lane];

    const float* __restrict__ acol = adj + m;

    float arr[KTOP];
#pragma unroll
    for (int j = 0; j < KTOP; j++) arr[j] = -FLT_MAX;

#define PAIR_AT(i) ((i) < SSTAGE ? sp[(i)] : __ldg(&pairs[(i)]))

    float aC[BATCH], aN[BATCH];

    // Prologue: adj loads for steps 0..7 of this parity stream
#pragma unroll
    for (int c = 0; c < BATCH; c++) {
        float2 p = PAIR_AT(2 * c + parity);
        aC[c] = __ldg(acol + (size_t)__float_as_int(p.y) * NN);
    }

    int base = 0;
    while (true) {
        const int nbase = base + BATCH;

        if (nbase < NSTEP) {   // prefetch next batch (8 independent LDGs)
#pragma unroll
            for (int c = 0; c < BATCH; c++) {
                float2 p = PAIR_AT(2 * (nbase + c) + parity);
                aN[c] = __ldg(acol + (size_t)__float_as_int(p.y) * NN);
            }
        }

        float lastx = 0.0f;
#pragma unroll
        for (int c = 0; c < BATCH; c++) {
            float2 p = PAIR_AT(2 * (base + c) + parity);
            float v = aC[c] * p.x;
            if (c == BATCH - 1) lastx = p.x;
            if (__any_sync(0xffffffffu, v > arr[KTOP - 1])) {
                float keep = v;
#pragma unroll
                for (int j = 0; j < KTOP; j++) {
                    float mx = fmaxf(arr[j], keep);
                    keep     = fminf(arr[j], keep);
                    arr[j]   = mx;
                }
            }
        }

        // Publish my 8th-largest; combine with partner's (monotone, stale-safe:
        // any read value lower-bounds partner's final arr[7] <= union 8th).
        *myThr = arr[KTOP - 1];
        float thr = fmaxf(arr[KTOP - 1], *otThr);

        bool more = (fmaxf(remaining_bound(lastx), 0.0f) > thr);
        base = nbase;
        if (base >= NSTEP || !__any_sync(0xffffffffu, more)) break;
#pragma unroll
        for (int c = 0; c < BATCH; c++) aC[c] = aN[c];
    }
#undef PAIR_AT

    // Odd-parity warps deposit results; even-parity warps merge + write.
    if (parity == 1) {
#pragma unroll
        for (int j = 0; j < KTOP; j++) smerge[pair][j][lane] = arr[j];
    }
    __syncthreads();

    if (parity == 0) {
        float L[KTOP];
#pragma unroll
        for (int j = 0; j < KTOP; j++)
            L[j] = fmaxf(arr[j], smerge[pair][KTOP - 1 - j][lane]);
        // half-cleaner sort (desc) of bitonic length-8 sequence
        CE(L[0], L[4]); CE(L[1], L[5]); CE(L[2], L[6]); CE(L[3], L[7]);
        CE(L[0], L[2]); CE(L[1], L[3]); CE(L[4], L[6]); CE(L[5], L[7]);
        CE(L[0], L[1]); CE(L[2], L[3]); CE(L[4], L[5]); CE(L[6], L[7]);

        float* o = out + (size_t)m * OUT_ROW + FF + f;
#pragma unroll
        for (int j = 0; j < KTOP; j++) o[j * FF] = L[j];
        // k=0 slice
        out[(size_t)m * OUT_ROW + f] = __ldg(&x[m * FF + f]);
    }
}

extern "C" void kernel_launch(void* const* d_in, const int* in_sizes, int n_in,
                              void* d_out, int out_size) {
    const float* x   = (const float*)d_in[0];
    const float* adj = (const float*)d_in[1];
    if (in_sizes[0] == NN * NN) {
        adj = (const float*)d_in[0];
        x   = (const float*)d_in[1];
    }
    float* out = (float*)d_out;

    bin_cols_kernel<<<FF, 512>>>(x);

    // 64 f * 16 blocks/f = 1024 blocks; 8 warps each (4 warp-pairs)
    topk_scan_kernel<<<1024, 256>>>(adj, x, out);
}

// round 6
// speedup vs baseline: 1.2000x; 1.2000x over previous
#include <cuda_runtime.h>
#include <cuda_bf16.h>
#include <cfloat>

#define NN 2048
#define FF 64
#define KTOP 8
#define OUT_ROW ((KTOP + 1) * FF)   // 576

#define NBINS 512
#define BIN_HI 4.25f
#define BIN_W  (8.5f / (float)NBINS)
#define BIN_INVW ((float)NBINS / 8.5f)

#define SSTAGE 1024     // candidates staged in smem per block
#define BATCH 16

// Scratch: per-feature candidate list (descending value-bins), split arrays.
__device__ float g_xval[FF * NN];   // candidate x value
__device__ int   g_off [FF * NN];   // candidate adj row offset (n * NN)

__device__ __forceinline__ int bin_of(float v) {
    int b = (int)((BIN_HI - v) * BIN_INVW);
    return max(0, min(NBINS - 1, b));
}
__device__ __forceinline__ float remaining_bound(float v) {
    int b = bin_of(v);
    return (b == 0) ? FLT_MAX : (BIN_HI - (float)b * BIN_W + 1e-3f);
}
__device__ __forceinline__ void CE(float& a, float& b) {
    float hi = fmaxf(a, b), lo = fminf(a, b); a = hi; b = lo;
}

// ---------------------------------------------------------------------------
// Kernel 1: per-feature bucket binning (proven structure; split-array output)
// ---------------------------------------------------------------------------
__global__ void __launch_bounds__(512) bin_cols_kernel(const float* __restrict__ x) {
    __shared__ float sx[NN];
    __shared__ int   cnt[NBINS];
    __shared__ int   sa[NBINS];
    __shared__ int   sb[NBINS];
    __shared__ int   cursor[NBINS];

    const int f   = blockIdx.x;
    const int tid = threadIdx.x;
    const int bs  = blockDim.x;

    for (int i = tid; i < NBINS; i += bs) cnt[i] = 0;
    __syncthreads();

    for (int i = tid; i < NN; i += bs) {
        float v = __ldg(&x[i * FF + f]);
        sx[i] = v;
        atomicAdd(&cnt[bin_of(v)], 1);
    }
    __syncthreads();

    for (int i = tid; i < NBINS; i += bs) sa[i] = cnt[i];
    __syncthreads();
    int* src = sa; int* dst = sb;
    for (int d = 1; d < NBINS; d <<= 1) {
        for (int i = tid; i < NBINS; i += bs)
            dst[i] = src[i] + ((i >= d) ? src[i - d] : 0);
        __syncthreads();
        int* t = src; src = dst; dst = t;
    }
    for (int i = tid; i < NBINS; i += bs) cursor[i] = src[i] - cnt[i];
    __syncthreads();

    float* oxv = g_xval + (size_t)f * NN;
    int*   oof = g_off  + (size_t)f * NN;
    for (int i = tid; i < NN; i += bs) {
        float v = sx[i];
        int pos = atomicAdd(&cursor[bin_of(v)], 1);
        oxv[pos] = v;
        oof[pos] = i * NN;
    }
}

// ---------------------------------------------------------------------------
// Kernel 2: pruned top-8 scan. One warp per (f, 32 consecutive m).
// Blocks of 128 threads (4 warps, same f). Grid 1024 -> 4096 warps.
// Steady state per candidate: LDS off + LDG + LDS xv + FMUL + FMAX.
// One vote per 16-candidate batch unless an insert is needed.
// ---------------------------------------------------------------------------
__global__ void __launch_bounds__(128, 8) topk_scan_kernel(
        const float* __restrict__ adj,
        const float* __restrict__ x,
        float* __restrict__ out) {
    __shared__ float sxv[SSTAGE];   // 4 KB
    __shared__ int   soff[SSTAGE];  // 4 KB

    const int f    = blockIdx.x >> 4;            // 16 blocks per feature
    const int mg   = (blockIdx.x & 15) * 4 + (threadIdx.x >> 5);
    const int lane = threadIdx.x & 31;
    const int m    = mg * 32 + lane;

    const float* __restrict__ gxv = g_xval + (size_t)f * NN;
    const int*   __restrict__ gof = g_off  + (size_t)f * NN;

    // Cooperative stage (block shares f)
    for (int i = threadIdx.x; i < SSTAGE; i += blockDim.x) {
        sxv[i]  = __ldg(&gxv[i]);
        soff[i] = __ldg(&gof[i]);
    }
    __syncthreads();

#define XV_AT(i)  ((i) < SSTAGE ? sxv[(i)]  : __ldg(&gxv[(i)]))
#define OFF_AT(i) ((i) < SSTAGE ? soff[(i)] : __ldg(&gof[(i)]))

    const float* __restrict__ acol = adj + m;

    float arr[KTOP];
#pragma unroll
    for (int j = 0; j < KTOP; j++) arr[j] = -FLT_MAX;

    float aC[BATCH], aN[BATCH];
#pragma unroll
    for (int c = 0; c < BATCH; c++)
        aC[c] = __ldg(acol + OFF_AT(c));

    int base = 0;
    while (true) {
        const int nbase = base + BATCH;

        if (nbase < NN) {   // prefetch next batch: 16 independent LDGs
#pragma unroll
            for (int c = 0; c < BATCH; c++)
                aN[c] = __ldg(acol + OFF_AT(nbase + c));
        }

        // Batch max of products (no stores of v)
        float vmax = -FLT_MAX;
#pragma unroll
        for (int c = 0; c < BATCH; c++)
            vmax = fmaxf(vmax, aC[c] * XV_AT(base + c));

        if (__any_sync(0xffffffffu, vmax > arr[KTOP - 1])) {
#pragma unroll
            for (int c = 0; c < BATCH; c++) {
                float v = aC[c] * XV_AT(base + c);
                if (__any_sync(0xffffffffu, v > arr[KTOP - 1])) {
                    float keep = v;
#pragma unroll
                    for (int j = 0; j < KTOP; j++) {
                        float mx = fmaxf(arr[j], keep);
                        keep     = fminf(arr[j], keep);
                        arr[j]   = mx;
                    }
                }
            }
        }

        // Remaining candidates bounded by batch-last bin's upper edge.
        bool more = (fmaxf(remaining_bound(XV_AT(nbase - 1)), 0.0f) > arr[KTOP - 1]);
        base = nbase;
        if (base >= NN || !__any_sync(0xffffffffu, more)) break;
#pragma unroll
        for (int c = 0; c < BATCH; c++) aC[c] = aN[c];
    }
#undef XV_AT
#undef OFF_AT

    // out[m, 1+j, f]
    float* o = out + (size_t)m * OUT_ROW + FF + f;
#pragma unroll
    for (int j = 0; j < KTOP; j++) o[j * FF] = arr[j];

    // k=0 slice: out[m, 0, f] = x[m, f]
    out[(size_t)m * OUT_ROW + f] = __ldg(&x[m * FF + f]);
}

extern "C" void kernel_launch(void* const* d_in, const int* in_sizes, int n_in,
                              void* d_out, int out_size) {
    const float* x   = (const float*)d_in[0];
    const float* adj = (const float*)d_in[1];
    if (in_sizes[0] == NN * NN) {
        adj = (const float*)d_in[0];
        x   = (const float*)d_in[1];
    }
    float* out = (float*)d_out;

    bin_cols_kernel<<<FF, 512>>>(x);

    // 64 f * 16 blocks/f = 1024 blocks of 128 threads (4 warps each)
    topk_scan_kernel<<<1024, 128>>>(adj, x, out);
}

// round 7
// speedup vs baseline: 1.3068x; 1.0890x over previous
#include <cuda_runtime.h>
#include <cuda_bf16.h>
#include <cfloat>

#define NN 2048
#define FF 64
#define KTOP 8
#define OUT_ROW ((KTOP + 1) * FF)   // 576

#define NBINS 512
#define BIN_HI 4.25f
#define BIN_W  (8.5f / (float)NBINS)
#define BIN_INVW ((float)NBINS / 8.5f)

#define SSTAGE 1024
#define BATCH 8

// Per-feature candidate lists, descending value-bins.
// g_pair: (x value, adj row element-offset n*NN as int bits)
// g_bnd : max(upper edge of this candidate's bin, 0) -> bound on ALL later products
__device__ float2 g_pair[FF * NN];   // 1 MB
__device__ float  g_bnd [FF * NN];   // 512 KB

__device__ __forceinline__ int bin_of(float v) {
    int b = (int)((BIN_HI - v) * BIN_INVW);
    return max(0, min(NBINS - 1, b));
}
__device__ __forceinline__ float remaining_bound(float v) {
    int b = bin_of(v);
    return (b == 0) ? FLT_MAX : (BIN_HI - (float)b * BIN_W + 1e-3f);
}

// ---------------------------------------------------------------------------
// Kernel 1: per-feature bucket binning; emits pair + precomputed bound.
// ---------------------------------------------------------------------------
__global__ void __launch_bounds__(512) bin_cols_kernel(const float* __restrict__ x) {
    __shared__ float sx[NN];
    __shared__ int   cnt[NBINS];
    __shared__ int   sa[NBINS];
    __shared__ int   sb[NBINS];
    __shared__ int   cursor[NBINS];

    const int f   = blockIdx.x;
    const int tid = threadIdx.x;
    const int bs  = blockDim.x;

    for (int i = tid; i < NBINS; i += bs) cnt[i] = 0;
    __syncthreads();

    for (int i = tid; i < NN; i += bs) {
        float v = __ldg(&x[i * FF + f]);
        sx[i] = v;
        atomicAdd(&cnt[bin_of(v)], 1);
    }
    __syncthreads();

    for (int i = tid; i < NBINS; i += bs) sa[i] = cnt[i];
    __syncthreads();
    int* src = sa; int* dst = sb;
    for (int d = 1; d < NBINS; d <<= 1) {
        for (int i = tid; i < NBINS; i += bs)
            dst[i] = src[i] + ((i >= d) ? src[i - d] : 0);
        __syncthreads();
        int* t = src; src = dst; dst = t;
    }
    for (int i = tid; i < NBINS; i += bs) cursor[i] = src[i] - cnt[i];
    __syncthreads();

    float2* op = g_pair + (size_t)f * NN;
    float*  ob = g_bnd  + (size_t)f * NN;
    for (int i = tid; i < NN; i += bs) {
        float v = sx[i];
        int pos = atomicAdd(&cursor[bin_of(v)], 1);
        op[pos] = make_float2(v, __int_as_float(i * NN));
        ob[pos] = fmaxf(remaining_bound(v), 0.0f);   // products of later cands <= this
    }
}

// ---------------------------------------------------------------------------
// Kernel 2: pruned top-8 scan. One warp per (f, 32 consecutive m).
// 256-thread blocks (8 warps, same f); 512 blocks -> 4096 warps.
// Hot loop: pure smem candidates, alternating A/B register buffers,
// x-values carried in registers from prefetch (no LDS in process phase).
// ---------------------------------------------------------------------------
__global__ void __launch_bounds__(256, 4) topk_scan_kernel(
        const float* __restrict__ adj,
        const float* __restrict__ x,
        float* __restrict__ out) {
    __shared__ float2 sp[SSTAGE];    // 8 KB
    __shared__ float  sbd[SSTAGE];   // 4 KB

    const int f    = blockIdx.x >> 3;              // 8 blocks per feature
    const int warp = threadIdx.x >> 5;
    const int lane = threadIdx.x & 31;
    const int mg   = (blockIdx.x & 7) * 8 + warp;  // 64 m-groups per feature
    const int m    = mg * 32 + lane;

    const float2* __restrict__ gp = g_pair + (size_t)f * NN;
    const float*  __restrict__ gb = g_bnd  + (size_t)f * NN;

    for (int i = threadIdx.x; i < SSTAGE; i += 256) {
        sp[i]  = __ldg(&gp[i]);
        sbd[i] = __ldg(&gb[i]);
    }
    __syncthreads();

    const float* __restrict__ acol = adj + m;

    float arr[KTOP];
#pragma unroll
    for (int j = 0; j < KTOP; j++) arr[j] = -FLT_MAX;

    float aA[BATCH], xA[BATCH], aB[BATCH], xB[BATCH];

#define PREF_S(XB, AB, b) do {                                              \
    _Pragma("unroll")                                                       \
    for (int c = 0; c < BATCH; c++) {                                       \
        float2 p = sp[(b) + c];                                             \
        XB[c] = p.x;                                                        \
        AB[c] = __ldg(acol + __float_as_int(p.y));                          \
    } } while (0)

#define PROC(XB, AB) do {                                                   \
    float v[BATCH];                                                         \
    _Pragma("unroll")                                                       \
    for (int c = 0; c < BATCH; c++) v[c] = AB[c] * XB[c];                   \
    float m01 = fmaxf(v[0], v[1]), m23 = fmaxf(v[2], v[3]);                 \
    float m45 = fmaxf(v[4], v[5]), m67 = fmaxf(v[6], v[7]);                 \
    float vmax = fmaxf(fmaxf(m01, m23), fmaxf(m45, m67));                   \
    if (__any_sync(0xffffffffu, vmax > arr[KTOP - 1])) {                    \
        _Pragma("unroll")                                                   \
        for (int c = 0; c < BATCH; c++) {                                   \
            if (__any_sync(0xffffffffu, v[c] > arr[KTOP - 1])) {            \
                float keep = v[c];                                          \
                _Pragma("unroll")                                           \
                for (int j = 0; j < KTOP; j++) {                            \
                    float mx = fmaxf(arr[j], keep);                         \
                    keep     = fminf(arr[j], keep);                         \
                    arr[j]   = mx;                                          \
                } } } } } while (0)

    // done when NO lane can still be improved by remaining candidates
#define TERM(b) (!__any_sync(0xffffffffu, sbd[(b) + BATCH - 1] > arr[KTOP - 1]))

    PREF_S(xA, aA, 0);
    int base = 0;
    bool fin = false;

    // Main pipelined loop: invariant at loop top = buffer A holds batch `base`.
    while (base + 3 * BATCH <= SSTAGE) {
        PREF_S(xB, aB, base + BATCH);
        PROC(xA, aA);
        if (TERM(base)) { fin = true; break; }
        base += BATCH;

        PREF_S(xA, aA, base + BATCH);
        PROC(xB, aB);
        if (TERM(base)) { fin = true; break; }
        base += BATCH;
    }

    if (!fin) {
        // A holds batch `base`; finish staged region without prefetch
        PROC(xA, aA);
        if (TERM(base)) fin = true;
        base += BATCH;
        while (!fin && base + BATCH <= SSTAGE) {
            PREF_S(xA, aA, base);
            PROC(xA, aA);
            if (TERM(base)) fin = true;
            base += BATCH;
        }
        // Global fallback (essentially never reached; bound ~0 by cand 1024)
        while (!fin && base + BATCH <= NN) {
#pragma unroll
            for (int c = 0; c < BATCH; c++) {
                float2 p = __ldg(&gp[base + c]);
                xA[c] = p.x;
                aA[c] = __ldg(acol + __float_as_int(p.y));
            }
            PROC(xA, aA);
            float bd = __ldg(&gb[base + BATCH - 1]);
            if (!__any_sync(0xffffffffu, bd > arr[KTOP - 1])) fin = true;
            base += BATCH;
        }
    }
#undef PREF_S
#undef PROC
#undef TERM

    // out[m, 1+j, f]
    float* o = out + (size_t)m * OUT_ROW + FF + f;
#pragma unroll
    for (int j = 0; j < KTOP; j++) o[j * FF] = arr[j];

    // k=0 slice: out[m, 0, f] = x[m, f]
    out[(size_t)m * OUT_ROW + f] = __ldg(&x[m * FF + f]);
}

extern "C" void kernel_launch(void* const* d_in, const int* in_sizes, int n_in,
                              void* d_out, int out_size) {
    const float* x   = (const float*)d_in[0];
    const float* adj = (const float*)d_in[1];
    if (in_sizes[0] == NN * NN) {
        adj = (const float*)d_in[0];
        x   = (const float*)d_in[1];
    }
    float* out = (float*)d_out;

    bin_cols_kernel<<<FF, 512>>>(x);

    // 64 f * 8 blocks/f = 512 blocks of 256 threads (8 warps each)
    topk_scan_kernel<<<512, 256>>>(adj, x, out);
}

// round 8
// speedup vs baseline: 1.4462x; 1.1067x over previous
#include <cuda_runtime.h>
#include <cuda_bf16.h>
#include <cfloat>

#define NN 2048
#define FF 64
#define KTOP 8
#define OUT_ROW ((KTOP + 1) * FF)   // 576

#define NBINS 512
#define BIN_HI 4.25f
#define BIN_W  (8.5f / (float)NBINS)
#define BIN_INVW ((float)NBINS / 8.5f)

#define SSTAGE 512
#define BATCH 8

// Per-feature candidate lists, descending value-bins (split arrays).
__device__ float g_xval[FF * NN];   // candidate x value
__device__ int   g_off [FF * NN];   // adj row element-offset (n * NN)
__device__ float g_bnd [FF * NN];   // max(bin upper edge, 0): bound on ALL later products

__device__ __forceinline__ int bin_of(float v) {
    int b = (int)((BIN_HI - v) * BIN_INVW);
    return max(0, min(NBINS - 1, b));
}
__device__ __forceinline__ float remaining_bound(float v) {
    int b = bin_of(v);
    return (b == 0) ? FLT_MAX : (BIN_HI - (float)b * BIN_W + 1e-3f);
}

// ---------------------------------------------------------------------------
// Kernel 1: per-feature bucket binning -> split arrays + precomputed bound
// ---------------------------------------------------------------------------
__global__ void __launch_bounds__(512) bin_cols_kernel(const float* __restrict__ x) {
    __shared__ float sx[NN];
    __shared__ int   cnt[NBINS];
    __shared__ int   sa[NBINS];
    __shared__ int   sb[NBINS];
    __shared__ int   cursor[NBINS];

    const int f   = blockIdx.x;
    const int tid = threadIdx.x;
    const int bs  = blockDim.x;

    for (int i = tid; i < NBINS; i += bs) cnt[i] = 0;
    __syncthreads();

    for (int i = tid; i < NN; i += bs) {
        float v = __ldg(&x[i * FF + f]);
        sx[i] = v;
        atomicAdd(&cnt[bin_of(v)], 1);
    }
    __syncthreads();

    for (int i = tid; i < NBINS; i += bs) sa[i] = cnt[i];
    __syncthreads();
    int* src = sa; int* dst = sb;
    for (int d = 1; d < NBINS; d <<= 1) {
        for (int i = tid; i < NBINS; i += bs)
            dst[i] = src[i] + ((i >= d) ? src[i - d] : 0);
        __syncthreads();
        int* t = src; src = dst; dst = t;
    }
    for (int i = tid; i < NBINS; i += bs) cursor[i] = src[i] - cnt[i];
    __syncthreads();

    float* oxv = g_xval + (size_t)f * NN;
    int*   oof = g_off  + (size_t)f * NN;
    float* obd = g_bnd  + (size_t)f * NN;
    for (int i = tid; i < NN; i += bs) {
        float v = sx[i];
        int pos = atomicAdd(&cursor[bin_of(v)], 1);
        oxv[pos] = v;
        oof[pos] = i * NN;
        obd[pos] = fmaxf(remaining_bound(v), 0.0f);
    }
}

// ---------------------------------------------------------------------------
// Kernel 2: pruned top-8 scan, depth-4 rotating prefetch (MLP=32 per warp).
// One warp per (f, 32 consecutive m); 128-thread blocks share f; grid 1024.
// ---------------------------------------------------------------------------
__global__ void __launch_bounds__(128, 8) topk_scan_kernel(
        const float* __restrict__ adj,
        const float* __restrict__ x,
        float* __restrict__ out) {
    __shared__ float sxv[SSTAGE];   // 2 KB
    __shared__ int   soff[SSTAGE];  // 2 KB
    __shared__ float sbd[SSTAGE];   // 2 KB

    const int f    = blockIdx.x >> 4;                        // 16 blocks/feature
    const int mg   = (blockIdx.x & 15) * 4 + (threadIdx.x >> 5);
    const int lane = threadIdx.x & 31;
    const int m    = mg * 32 + lane;

    const float* __restrict__ gxv = g_xval + (size_t)f * NN;
    const int*   __restrict__ gof = g_off  + (size_t)f * NN;
    const float* __restrict__ gbd = g_bnd  + (size_t)f * NN;

    for (int i = threadIdx.x; i < SSTAGE; i += 128) {
        sxv[i]  = __ldg(&gxv[i]);
        soff[i] = __ldg(&gof[i]);
        sbd[i]  = __ldg(&gbd[i]);
    }
    __syncthreads();

    const float* __restrict__ acol = adj + m;

    float arr[KTOP];
#pragma unroll
    for (int j = 0; j < KTOP; j++) arr[j] = -FLT_MAX;

    float a0[BATCH], a1[BATCH], a2[BATCH], a3[BATCH];

#define PREF(AB, b) do {                                                    \
    _Pragma("unroll")                                                       \
    for (int c = 0; c < BATCH; c++)                                         \
        AB[c] = __ldg(acol + soff[(b) + c]);                                \
    } while (0)

#define PROC(AB, b) do {                                                    \
    float v[BATCH];                                                         \
    _Pragma("unroll")                                                       \
    for (int c = 0; c < BATCH; c++) v[c] = AB[c] * sxv[(b) + c];            \
    float m01 = fmaxf(v[0], v[1]), m23 = fmaxf(v[2], v[3]);                 \
    float m45 = fmaxf(v[4], v[5]), m67 = fmaxf(v[6], v[7]);                 \
    float vmax = fmaxf(fmaxf(m01, m23), fmaxf(m45, m67));                   \
    if (__any_sync(0xffffffffu, vmax > arr[KTOP - 1])) {                    \
        _Pragma("unroll")                                                   \
        for (int c = 0; c < BATCH; c++) {                                   \
            if (__any_sync(0xffffffffu, v[c] > arr[KTOP - 1])) {            \
                float keep = v[c];                                          \
                _Pragma("unroll")                                           \
                for (int j = 0; j < KTOP; j++) {                            \
                    float mx = fmaxf(arr[j], keep);                         \
                    keep     = fminf(arr[j], keep);                         \
                    arr[j]   = mx;                                          \
                } } } } } while (0)

#define TERM(b) (!__any_sync(0xffffffffu, sbd[(b) + BATCH - 1] > arr[KTOP - 1]))

    PREF(a0, 0); PREF(a1, BATCH); PREF(a2, 2 * BATCH); PREF(a3, 3 * BATCH);

    int base = 0;
    bool fin = false;

    // Steady state: 4 batches (32 loads) always in flight.
    while (base + 5 * BATCH <= SSTAGE) {
        PROC(a0, base); if (TERM(base)) { fin = true; break; }
        PREF(a0, base + 4 * BATCH); base += BATCH;
        PROC(a1, base); if (TERM(base)) { fin = true; break; }
        PREF(a1, base + 4 * BATCH); base += BATCH;
        PROC(a2, base); if (TERM(base)) { fin = true; break; }
        PREF(a2, base + 4 * BATCH); base += BATCH;
        PROC(a3, base); if (TERM(base)) { fin = true; break; }
        PREF(a3, base + 4 * BATCH); base += BATCH;
    }

    if (!fin) {   // drain: buffers hold base .. base+31 (exactly to SSTAGE)
        PROC(a0, base); fin = TERM(base); base += BATCH;
        if (!fin) { PROC(a1, base); fin = TERM(base); base += BATCH; }
        if (!fin) { PROC(a2, base); fin = TERM(base); base += BATCH; }
        if (!fin) { PROC(a3, base); fin = TERM(base); base += BATCH; }
    }

    // Global fallback (rarely reached; exactness guarantee)
    while (!fin && base + BATCH <= NN) {
        float xg[BATCH];
#pragma unroll
        for (int c = 0; c < BATCH; c++) {
            a0[c] = __ldg(acol + __ldg(&gof[base + c]));
            xg[c] = __ldg(&gxv[base + c]);
        }
        float v[BATCH];
#pragma unroll
        for (int c = 0; c < BATCH; c++) v[c] = a0[c] * xg[c];
#pragma unroll
        for (int c = 0; c < BATCH; c++) {
            if (__any_sync(0xffffffffu, v[c] > arr[KTOP - 1])) {
                float keep = v[c];
#pragma unroll
                for (int j = 0; j < KTOP; j++) {
                    float mx = fmaxf(arr[j], keep);
                    keep     = fminf(arr[j], keep);
                    arr[j]   = mx;
                }
            }
        }
        float bd = __ldg(&gbd[base + BATCH - 1]);
        if (!__any_sync(0xffffffffu, bd > arr[KTOP - 1])) fin = true;
        base += BATCH;
    }
#undef PREF
#undef PROC
#undef TERM

    // out[m, 1+j, f]
    float* o = out + (size_t)m * OUT_ROW + FF + f;
#pragma unroll
    for (int j = 0; j < KTOP; j++) o[j * FF] = arr[j];

    // k=0 slice: out[m, 0, f] = x[m, f]
    out[(size_t)m * OUT_ROW + f] = __ldg(&x[m * FF + f]);
}

extern "C" void kernel_launch(void* const* d_in, const int* in_sizes, int n_in,
                              void* d_out, int out_size) {
    const float* x   = (const float*)d_in[0];
    const float* adj = (const float*)d_in[1];
    if (in_sizes[0] == NN * NN) {
        adj = (const float*)d_in[0];
        x   = (const float*)d_in[1];
    }
    float* out = (float*)d_out;

    bin_cols_kernel<<<FF, 512>>>(x);

    // 64 f * 16 blocks/f = 1024 blocks of 128 threads (4 warps each)
    topk_scan_kernel<<<1024, 128>>>(adj, x, out);
}